// round 13
// baseline (speedup 1.0000x reference)
#include <cuda_runtime.h>
#include <cuda_fp16.h>
#include <cstdint>
#include <math.h>

#define D     64
#define MAXN  8192
#define BM    64
#define BN    128

// sum_kernel dynamic smem: 3 K buffers + Q stage
#define S_QOFF   49152
#define S_SMEM   (S_QOFF + 8192)          // 57344

// strip_kernel dynamic smem: 3 E bufs (16KB) + 3 V bufs (16KB)
#define T_VOFF   49152
#define T_SMEM   98304

// Scratch (allocation-free contract: __device__ globals)
__device__ __align__(16) __half g_Qh[(size_t)MAXN * D];
__device__ __align__(16) __half g_Kh[(size_t)MAXN * D];
__device__ __align__(16) __half g_Vh[(size_t)MAXN * D];
__device__ float g_rowsum[MAXN];
__device__ float g_invsum[MAXN];
__device__ float g_Opart[2][(size_t)MAXN * D];
// E scratch in fragment layout: per tile 4096 uint32 =
// [g16 0..3][kc 0..7][lane 0..31][slot 0..3]
__device__ __align__(16) uint32_t g_E[(size_t)(MAXN / 64) * (MAXN / 128) * 4096];

__device__ __forceinline__ float load_hyper_c(const int* hc) {
    int iv = hc[0];
    if (iv > 1000000 || iv < -1000000) return __int_as_float(iv);
    return (float)iv;
}

__device__ __forceinline__ uint32_t smem_u32(const void* p) {
    return (uint32_t)__cvta_generic_to_shared(p);
}

// Swizzled byte offset inside a tile whose rows are 128B (64 halves).
__device__ __forceinline__ uint32_t swz(int row, int colbyte) {
    return (uint32_t)(row * 128 + (colbyte ^ ((row & 7) << 4)));
}

__device__ __forceinline__ void ldsm_x4(uint32_t& r0, uint32_t& r1,
                                        uint32_t& r2, uint32_t& r3,
                                        uint32_t addr) {
    asm volatile("ldmatrix.sync.aligned.m8n8.x4.shared.b16 {%0,%1,%2,%3}, [%4];\n"
                 : "=r"(r0), "=r"(r1), "=r"(r2), "=r"(r3) : "r"(addr));
}

__device__ __forceinline__ void ldsm_x4_trans(uint32_t& r0, uint32_t& r1,
                                              uint32_t& r2, uint32_t& r3,
                                              uint32_t addr) {
    asm volatile("ldmatrix.sync.aligned.m8n8.x4.trans.shared.b16 {%0,%1,%2,%3}, [%4];\n"
                 : "=r"(r0), "=r"(r1), "=r"(r2), "=r"(r3) : "r"(addr));
}

__device__ __forceinline__ void lds128(uint32_t u[4], uint32_t addr) {
    asm volatile("ld.shared.v4.b32 {%0,%1,%2,%3}, [%4];\n"
                 : "=r"(u[0]), "=r"(u[1]), "=r"(u[2]), "=r"(u[3]) : "r"(addr));
}

__device__ __forceinline__ void mma_f16(float d[4], const uint32_t a[4],
                                        uint32_t b0, uint32_t b1) {
    asm volatile(
        "mma.sync.aligned.m16n8k16.row.col.f32.f16.f16.f32 "
        "{%0,%1,%2,%3}, {%4,%5,%6,%7}, {%8,%9}, {%0,%1,%2,%3};\n"
        : "+f"(d[0]), "+f"(d[1]), "+f"(d[2]), "+f"(d[3])
        : "r"(a[0]), "r"(a[1]), "r"(a[2]), "r"(a[3]), "r"(b0), "r"(b1));
}

__device__ __forceinline__ void cp_async16(uint32_t smem_dst, const void* gmem_src) {
    asm volatile("cp.async.cg.shared.global [%0], [%1], 16;\n"
                 :: "r"(smem_dst), "l"(gmem_src) : "memory");
}
__device__ __forceinline__ void cp_commit() {
    asm volatile("cp.async.commit_group;\n" ::: "memory");
}
__device__ __forceinline__ void cp_wait1() {
    asm volatile("cp.async.wait_group 1;\n" ::: "memory");
}

// streaming (evict-first) float2 store: keep p out of L2 so E stays resident
__device__ __forceinline__ void stcs_f2(float* p, float x, float y) {
    asm volatile("st.global.cs.v2.f32 [%0], {%1,%2};\n"
                 :: "l"(p), "f"(x), "f"(y) : "memory");
}

// ---------------------------------------------------------------------------
// Kernel 1: normalize Q,K rows -> fp16; convert V -> fp16; zero g_rowsum.
// ---------------------------------------------------------------------------
__global__ void prep_kernel(const float* __restrict__ q,
                            const float* __restrict__ k,
                            const float* __restrict__ v,
                            int N, int M) {
    int gt = blockIdx.x * blockDim.x + threadIdx.x;
    if (gt < MAXN) g_rowsum[gt] = 0.0f;

    int gw   = gt >> 5;
    int lane = threadIdx.x & 31;
    if (gw >= N + 2 * M) return;

    const float* src;
    __half* dst;
    bool nrm = true;
    if (gw < N)          { src = q + (size_t)gw * D;               dst = g_Qh + (size_t)gw * D; }
    else if (gw < N + M) { size_t r = gw - N;     src = k + r * D; dst = g_Kh + r * D; }
    else                 { size_t r = gw - N - M; src = v + r * D; dst = g_Vh + r * D; nrm = false; }

    float2 val = reinterpret_cast<const float2*>(src)[lane];
    float inv = 1.0f;
    if (nrm) {
        float ss = val.x * val.x + val.y * val.y;
#pragma unroll
        for (int o = 16; o > 0; o >>= 1) ss += __shfl_xor_sync(0xffffffffu, ss, o);
        inv = rsqrtf(ss);
    }
    reinterpret_cast<__half2*>(dst)[lane] = __floats2half2_rn(val.x * inv, val.y * inv);
}

// ---------------------------------------------------------------------------
// Kernel 2: QK + exp + partial rowsums. Key-split grid (N/64, 2).
// Stores raw e (fp16) to g_E in FRAGMENT layout; rowsums via global atomics.
// ---------------------------------------------------------------------------
__global__ __launch_bounds__(256)
void sum_kernel(const int* __restrict__ hc, int N, int M) {
    extern __shared__ __align__(16) char smem_raw[];
    const uint32_t sb = smem_u32(smem_raw);
    __shared__ float rowsum_s[BM];

    const int tid  = threadIdx.x;
    const int lane = tid & 31;
    const int wid  = tid >> 5;
    const int rg   = wid >> 2;
    const int kg   = wid & 3;
    const int g    = lane >> 2;
    const int t    = lane & 3;
    const int j    = lane >> 3;
    const int jr   = lane & 7;
    const int r0   = blockIdx.x * BM;
    const int ks   = blockIdx.y;
    const int kb0g = ks * (M >> 1);
    const float c  = load_hyper_c(hc);
    const float negc = -c;

    if (tid < BM) rowsum_s[tid] = 0.0f;

    const int T = M / (2 * BN);
    const size_t tile0 = (size_t)(r0 >> 6) * (M / BN) + (size_t)ks * T;

#pragma unroll
    for (int p = 0; p < 2; p++) {
        if (p < T) {
#pragma unroll
            for (int w = 0; w < 4; w++) {
                int chunk = tid + w * 256;
                int row = chunk >> 3, c8 = chunk & 7;
                cp_async16(sb + (uint32_t)(p * 16384) + swz(row, c8 * 16),
                           g_Kh + (size_t)(kb0g + p * BN + row) * D + c8 * 8);
            }
        }
        cp_commit();
    }

#pragma unroll
    for (int w = 0; w < 2; w++) {
        int chunk = tid + w * 256;
        int row = chunk >> 3, c8 = chunk & 7;
        uint4 val = reinterpret_cast<const uint4*>(g_Qh + (size_t)(r0 + row) * D)[c8];
        *reinterpret_cast<uint4*>(smem_raw + S_QOFF + swz(row, c8 * 16)) = val;
    }
    __syncthreads();

    uint32_t qa[4][2][4];
#pragma unroll
    for (int kc = 0; kc < 4; kc++) {
#pragma unroll
        for (int f = 0; f < 2; f++) {
            int row = rg * 32 + f * 16 + (j & 1) * 8 + jr;
            int col = kc * 16 + (j >> 1) * 8;
            ldsm_x4(qa[kc][f][0], qa[kc][f][1], qa[kc][f][2], qa[kc][f][3],
                    sb + S_QOFF + swz(row, col * 2));
        }
    }

    float rs[2][2] = {{0.f, 0.f}, {0.f, 0.f}};

    for (int tt = 0; tt < T; tt++) {
        const uint32_t cb = sb + (uint32_t)((tt % 3) * 16384);
        cp_wait1();
        __syncthreads();

        if (tt + 2 < T) {
            const uint32_t nb = sb + (uint32_t)(((tt + 2) % 3) * 16384);
            const int mn = (tt + 2) * BN;
#pragma unroll
            for (int w = 0; w < 4; w++) {
                int chunk = tid + w * 256;
                int row = chunk >> 3, c8 = chunk & 7;
                cp_async16(nb + swz(row, c8 * 16),
                           g_Kh + (size_t)(kb0g + mn + row) * D + c8 * 8);
            }
        }
        cp_commit();

        float sacc[2][4][4];
#pragma unroll
        for (int f = 0; f < 2; f++)
#pragma unroll
            for (int nt = 0; nt < 4; nt++)
#pragma unroll
                for (int jj = 0; jj < 4; jj++) sacc[f][nt][jj] = 0.0f;

#pragma unroll
        for (int kc = 0; kc < 4; kc++) {
#pragma unroll
            for (int ntp = 0; ntp < 2; ntp++) {
                uint32_t b0, b1, b2, b3;
                int key = kg * 32 + (2 * ntp + (j >> 1)) * 8 + jr;
                int col = kc * 16 + (j & 1) * 8;
                ldsm_x4(b0, b1, b2, b3, cb + swz(key, col * 2));
#pragma unroll
                for (int f = 0; f < 2; f++) {
                    mma_f16(sacc[f][2 * ntp + 0], qa[kc][f], b0, b1);
                    mma_f16(sacc[f][2 * ntp + 1], qa[kc][f], b2, b3);
                }
            }
        }

        // exp + rowsum + fragment-layout E store (raw e, fp16, uint4 STG)
        uint32_t* tb = g_E + (tile0 + tt) * 4096;
#pragma unroll
        for (int f = 0; f < 2; f++) {
            int g16 = rg * 2 + f;
#pragma unroll
            for (int ntp = 0; ntp < 2; ntp++) {
                float e0 = __expf(fmaf(c, sacc[f][2 * ntp][0], negc));
                float e1 = __expf(fmaf(c, sacc[f][2 * ntp][1], negc));
                float e2 = __expf(fmaf(c, sacc[f][2 * ntp][2], negc));
                float e3 = __expf(fmaf(c, sacc[f][2 * ntp][3], negc));
                float o0 = __expf(fmaf(c, sacc[f][2 * ntp + 1][0], negc));
                float o1 = __expf(fmaf(c, sacc[f][2 * ntp + 1][1], negc));
                float o2 = __expf(fmaf(c, sacc[f][2 * ntp + 1][2], negc));
                float o3 = __expf(fmaf(c, sacc[f][2 * ntp + 1][3], negc));
                rs[f][0] += (e0 + e1) + (o0 + o1);
                rs[f][1] += (e2 + e3) + (o2 + o3);
                __half2 he01 = __floats2half2_rn(e0, e1);
                __half2 he23 = __floats2half2_rn(e2, e3);
                __half2 ho01 = __floats2half2_rn(o0, o1);
                __half2 ho23 = __floats2half2_rn(o2, o3);
                uint4 pack;
                pack.x = *reinterpret_cast<uint32_t*>(&he01);
                pack.y = *reinterpret_cast<uint32_t*>(&he23);
                pack.z = *reinterpret_cast<uint32_t*>(&ho01);
                pack.w = *reinterpret_cast<uint32_t*>(&ho23);
                uint32_t* dst = tb + g16 * 1024 + (kg * 2 + ntp) * 128 + lane * 4;
                *reinterpret_cast<uint4*>(dst) = pack;
            }
        }
    }

#pragma unroll
    for (int f = 0; f < 2; f++) {
#pragma unroll
        for (int o = 1; o <= 2; o <<= 1) {
            rs[f][0] += __shfl_xor_sync(0xffffffffu, rs[f][0], o);
            rs[f][1] += __shfl_xor_sync(0xffffffffu, rs[f][1], o);
        }
        if (t == 0) {
            atomicAdd(&rowsum_s[rg * 32 + f * 16 + g], rs[f][0]);
            atomicAdd(&rowsum_s[rg * 32 + f * 16 + g + 8], rs[f][1]);
        }
    }
    __syncthreads();

    if (tid < BM) atomicAdd(&g_rowsum[r0 + tid], rowsum_s[tid]);
}

// ---------------------------------------------------------------------------
// Kernel 2b: invert rowsums.
// ---------------------------------------------------------------------------
__global__ void inv_kernel(int N) {
    int i = blockIdx.x * blockDim.x + threadIdx.x;
    if (i < N) g_invsum[i] = 1.0f / g_rowsum[i];
}

// ---------------------------------------------------------------------------
// Kernel 3: streaming PV + p writeback. Key-split grid (N/64, 2).
// E tiles read linear (fragment layout -> LDS.128 A-frags), V via ldmatrix.
// O partials to g_Opart[ks]; p stores streaming (.cs).
// ---------------------------------------------------------------------------
__global__ __launch_bounds__(256)
void strip_kernel(float* __restrict__ out_p, int N, int M) {
    extern __shared__ __align__(16) char smem_raw[];
    const uint32_t sb = smem_u32(smem_raw);

    const int tid  = threadIdx.x;
    const int lane = tid & 31;
    const int wid  = tid >> 5;
    const int rg   = wid >> 1;     // 0..3: rows [rg*16, rg*16+16)
    const int dg   = wid & 1;      // 0..1: d cols [dg*32, dg*32+32)
    const int g    = lane >> 2;
    const int t    = lane & 3;
    const int j    = lane >> 3;
    const int jr   = lane & 7;
    const int r0   = blockIdx.x * BM;
    const int ks   = blockIdx.y;
    const int kb0g = ks * (M >> 1);

    const float inv_lo = g_invsum[r0 + rg * 16 + g];
    const float inv_hi = g_invsum[r0 + rg * 16 + g + 8];

    const int T = M / (2 * BN);
    const size_t tile0 = (size_t)(r0 >> 6) * (M / BN) + (size_t)ks * T;
    const char* ebase_g = reinterpret_cast<const char*>(g_E);

    // prologue: prefetch E (linear) and V (swizzled) tiles 0,1
#pragma unroll
    for (int p = 0; p < 2; p++) {
        if (p < T) {
            const char* esrc = ebase_g + (tile0 + p) * 16384;
#pragma unroll
            for (int w = 0; w < 4; w++) {
                int ch = tid + w * 256;               // 0..1023
                cp_async16(sb + (uint32_t)(p * 16384 + ch * 16), esrc + ch * 16);
                int row = ch >> 3, c8 = ch & 7;
                cp_async16(sb + (uint32_t)(T_VOFF + p * 16384) + swz(row, c8 * 16),
                           g_Vh + (size_t)(kb0g + p * BN + row) * D + c8 * 8);
            }
        }
        cp_commit();
    }

    float oacc[4][4];
#pragma unroll
    for (int n = 0; n < 4; n++)
#pragma unroll
        for (int jj = 0; jj < 4; jj++) oacc[n][jj] = 0.0f;

    for (int tt = 0; tt < T; tt++) {
        const uint32_t eb = sb + (uint32_t)((tt % 3) * 16384);
        const uint32_t vb = sb + (uint32_t)(T_VOFF + (tt % 3) * 16384);
        const int m0g = kb0g + tt * BN;

        cp_wait1();
        __syncthreads();

        if (tt + 2 < T) {
            const char* esrc = ebase_g + (tile0 + tt + 2) * 16384;
            const uint32_t ne = sb + (uint32_t)(((tt + 2) % 3) * 16384);
            const uint32_t nv = sb + (uint32_t)(T_VOFF + ((tt + 2) % 3) * 16384);
            const int mn = (tt + 2) * BN;
#pragma unroll
            for (int w = 0; w < 4; w++) {
                int ch = tid + w * 256;
                cp_async16(ne + ch * 16, esrc + ch * 16);
                int row = ch >> 3, c8 = ch & 7;
                cp_async16(nv + swz(row, c8 * 16),
                           g_Vh + (size_t)(kb0g + mn + row) * D + c8 * 8);
            }
        }
        cp_commit();

#pragma unroll
        for (int kc = 0; kc < 8; kc++) {
            // A-fragment: direct LDS.128 from fragment-layout E tile
            uint32_t u[4];
            lds128(u, eb + (uint32_t)(rg * 4096 + kc * 512 + lane * 16));

            // B-fragments: V tile, 16 keys x 32 d for this kc/dg
            uint32_t b0, b1, b2, b3, c0, c1, c2, c3;
            int key = kc * 16 + (j & 1) * 8 + jr;
            ldsm_x4_trans(b0, b1, b2, b3,
                          vb + swz(key, (dg * 4 + 0 + (j >> 1)) * 16));
            ldsm_x4_trans(c0, c1, c2, c3,
                          vb + swz(key, (dg * 4 + 2 + (j >> 1)) * 16));
            mma_f16(oacc[0], u, b0, b1);
            mma_f16(oacc[1], u, b2, b3);
            mma_f16(oacc[2], u, c0, c1);
            mma_f16(oacc[3], u, c2, c3);

            // p writeback (streaming): each dg warp handles 4 of 8 key-chunks
            if ((kc >> 2) == dg) {
                float2 f0 = __half22float2(*reinterpret_cast<__half2*>(&u[0]));
                float2 f1 = __half22float2(*reinterpret_cast<__half2*>(&u[1]));
                float2 f2 = __half22float2(*reinterpret_cast<__half2*>(&u[2]));
                float2 f3 = __half22float2(*reinterpret_cast<__half2*>(&u[3]));
                size_t rlo = (size_t)(r0 + rg * 16 + g) * M;
                size_t rhi = rlo + 8 * (size_t)M;
                int colb = m0g + kc * 16 + 2 * t;
                stcs_f2(out_p + rlo + colb,     f0.x * inv_lo, f0.y * inv_lo);
                stcs_f2(out_p + rhi + colb,     f1.x * inv_hi, f1.y * inv_hi);
                stcs_f2(out_p + rlo + colb + 8, f2.x * inv_lo, f2.y * inv_lo);
                stcs_f2(out_p + rhi + colb + 8, f3.x * inv_hi, f3.y * inv_hi);
            }
        }
    }

    // O epilogue: partials per key-split; each warp owns disjoint rows x cols.
    float* opart = g_Opart[ks];
    int rowlo = r0 + rg * 16 + g;
#pragma unroll
    for (int n = 0; n < 4; n++) {
        int col = dg * 32 + n * 8 + 2 * t;
        *reinterpret_cast<float2*>(opart + (size_t)rowlo * D + col) =
            make_float2(oacc[n][0] * inv_lo, oacc[n][1] * inv_lo);
        *reinterpret_cast<float2*>(opart + (size_t)(rowlo + 8) * D + col) =
            make_float2(oacc[n][2] * inv_hi, oacc[n][3] * inv_hi);
    }
}

// ---------------------------------------------------------------------------
// Kernel 4: combine O partials -> out_res.
// ---------------------------------------------------------------------------
__global__ void combine_kernel(float* __restrict__ out_res, int total4) {
    int i = blockIdx.x * blockDim.x + threadIdx.x;
    if (i >= total4) return;
    float4 a = reinterpret_cast<const float4*>(g_Opart[0])[i];
    float4 b = reinterpret_cast<const float4*>(g_Opart[1])[i];
    reinterpret_cast<float4*>(out_res)[i] =
        make_float4(a.x + b.x, a.y + b.y, a.z + b.z, a.w + b.w);
}

// ---------------------------------------------------------------------------
extern "C" void kernel_launch(void* const* d_in, const int* in_sizes, int n_in,
                              void* d_out, int out_size) {
    const float* q  = (const float*)d_in[0];
    const float* k  = (const float*)d_in[1];
    const float* v  = (const float*)d_in[2];
    const int*   hc = (const int*)d_in[3];

    int N = in_sizes[0] / D;
    int M = in_sizes[1] / D;

    float* out_res = (float*)d_out;                      // [N, D]
    float* out_p   = (float*)d_out + (size_t)N * D;      // [N, M]

    static bool attr_set = false;
    if (!attr_set) {
        cudaFuncSetAttribute(sum_kernel,
                             cudaFuncAttributeMaxDynamicSharedMemorySize, S_SMEM);
        cudaFuncSetAttribute(strip_kernel,
                             cudaFuncAttributeMaxDynamicSharedMemorySize, T_SMEM);
        attr_set = true;
    }

    int rows = N + 2 * M;
    int prep_blocks = (rows * 32 + 255) / 256;
    prep_kernel<<<prep_blocks, 256>>>(q, k, v, N, M);

    dim3 sgrid(N / BM, 2);
    sum_kernel<<<sgrid, 256, S_SMEM>>>(hc, N, M);
    inv_kernel<<<(N + 255) / 256, 256>>>(N);
    strip_kernel<<<sgrid, 256, T_SMEM>>>(out_p, N, M);

    int total4 = N * D / 4;
    combine_kernel<<<(total4 + 255) / 256, 256>>>(out_res, total4);
}

// round 14
// speedup vs baseline: 1.0030x; 1.0030x over previous
#include <cuda_runtime.h>
#include <cuda_fp16.h>
#include <cstdint>
#include <math.h>

#define D     64
#define MAXN  8192
#define BM    64
#define BN    128

// sum_kernel dynamic smem: 3 K buffers + Q stage
#define S_QOFF   49152
#define S_SMEM   (S_QOFF + 8192)          // 57344

// strip_kernel dynamic smem: 3 E bufs (16KB) + 3 V bufs (16KB)
#define T_VOFF   49152
#define T_SMEM   98304

// Scratch (allocation-free contract: __device__ globals)
__device__ __align__(16) __half g_Qh[(size_t)MAXN * D];
__device__ __align__(16) __half g_Kh[(size_t)MAXN * D];
__device__ __align__(16) __half g_Vh[(size_t)MAXN * D];
__device__ float g_rowsum[MAXN];
__device__ float g_invsum[MAXN];
// E scratch in fragment layout: per tile 4096 uint32 =
// [g16 0..3][kc 0..7][lane 0..31][slot 0..3]
__device__ __align__(16) uint32_t g_E[(size_t)(MAXN / 64) * (MAXN / 128) * 4096];

__device__ __forceinline__ float load_hyper_c(const int* hc) {
    int iv = hc[0];
    if (iv > 1000000 || iv < -1000000) return __int_as_float(iv);
    return (float)iv;
}

__device__ __forceinline__ uint32_t smem_u32(const void* p) {
    return (uint32_t)__cvta_generic_to_shared(p);
}

// Swizzled byte offset inside a tile whose rows are 128B (64 halves).
__device__ __forceinline__ uint32_t swz(int row, int colbyte) {
    return (uint32_t)(row * 128 + (colbyte ^ ((row & 7) << 4)));
}

__device__ __forceinline__ void ldsm_x4(uint32_t& r0, uint32_t& r1,
                                        uint32_t& r2, uint32_t& r3,
                                        uint32_t addr) {
    asm volatile("ldmatrix.sync.aligned.m8n8.x4.shared.b16 {%0,%1,%2,%3}, [%4];\n"
                 : "=r"(r0), "=r"(r1), "=r"(r2), "=r"(r3) : "r"(addr));
}

__device__ __forceinline__ void ldsm_x4_trans(uint32_t& r0, uint32_t& r1,
                                              uint32_t& r2, uint32_t& r3,
                                              uint32_t addr) {
    asm volatile("ldmatrix.sync.aligned.m8n8.x4.trans.shared.b16 {%0,%1,%2,%3}, [%4];\n"
                 : "=r"(r0), "=r"(r1), "=r"(r2), "=r"(r3) : "r"(addr));
}

__device__ __forceinline__ void lds128(uint32_t u[4], uint32_t addr) {
    asm volatile("ld.shared.v4.b32 {%0,%1,%2,%3}, [%4];\n"
                 : "=r"(u[0]), "=r"(u[1]), "=r"(u[2]), "=r"(u[3]) : "r"(addr));
}

__device__ __forceinline__ void mma_f16(float d[4], const uint32_t a[4],
                                        uint32_t b0, uint32_t b1) {
    asm volatile(
        "mma.sync.aligned.m16n8k16.row.col.f32.f16.f16.f32 "
        "{%0,%1,%2,%3}, {%4,%5,%6,%7}, {%8,%9}, {%0,%1,%2,%3};\n"
        : "+f"(d[0]), "+f"(d[1]), "+f"(d[2]), "+f"(d[3])
        : "r"(a[0]), "r"(a[1]), "r"(a[2]), "r"(a[3]), "r"(b0), "r"(b1));
}

__device__ __forceinline__ void cp_async16(uint32_t smem_dst, const void* gmem_src) {
    asm volatile("cp.async.cg.shared.global [%0], [%1], 16;\n"
                 :: "r"(smem_dst), "l"(gmem_src) : "memory");
}
__device__ __forceinline__ void cp_commit() {
    asm volatile("cp.async.commit_group;\n" ::: "memory");
}
__device__ __forceinline__ void cp_wait1() {
    asm volatile("cp.async.wait_group 1;\n" ::: "memory");
}

// streaming (evict-first) float2 store: keep p out of L2 so E stays resident
__device__ __forceinline__ void stcs_f2(float* p, float x, float y) {
    asm volatile("st.global.cs.v2.f32 [%0], {%1,%2};\n"
                 :: "l"(p), "f"(x), "f"(y) : "memory");
}

// ---------------------------------------------------------------------------
// Kernel 1: normalize Q,K rows -> fp16; convert V -> fp16; zero g_rowsum.
// ---------------------------------------------------------------------------
__global__ void prep_kernel(const float* __restrict__ q,
                            const float* __restrict__ k,
                            const float* __restrict__ v,
                            int N, int M) {
    int gt = blockIdx.x * blockDim.x + threadIdx.x;
    if (gt < MAXN) g_rowsum[gt] = 0.0f;

    int gw   = gt >> 5;
    int lane = threadIdx.x & 31;
    if (gw >= N + 2 * M) return;

    const float* src;
    __half* dst;
    bool nrm = true;
    if (gw < N)          { src = q + (size_t)gw * D;               dst = g_Qh + (size_t)gw * D; }
    else if (gw < N + M) { size_t r = gw - N;     src = k + r * D; dst = g_Kh + r * D; }
    else                 { size_t r = gw - N - M; src = v + r * D; dst = g_Vh + r * D; nrm = false; }

    float2 val = reinterpret_cast<const float2*>(src)[lane];
    float inv = 1.0f;
    if (nrm) {
        float ss = val.x * val.x + val.y * val.y;
#pragma unroll
        for (int o = 16; o > 0; o >>= 1) ss += __shfl_xor_sync(0xffffffffu, ss, o);
        inv = rsqrtf(ss);
    }
    reinterpret_cast<__half2*>(dst)[lane] = __floats2half2_rn(val.x * inv, val.y * inv);
}

// ---------------------------------------------------------------------------
// Kernel 2: QK + exp + partial rowsums. Key-split grid (N/64, 2).
// Stores raw e (fp16) to g_E in FRAGMENT layout; rowsums via global atomics.
// ---------------------------------------------------------------------------
__global__ __launch_bounds__(256)
void sum_kernel(const int* __restrict__ hc, int N, int M) {
    extern __shared__ __align__(16) char smem_raw[];
    const uint32_t sb = smem_u32(smem_raw);
    __shared__ float rowsum_s[BM];

    const int tid  = threadIdx.x;
    const int lane = tid & 31;
    const int wid  = tid >> 5;
    const int rg   = wid >> 2;
    const int kg   = wid & 3;
    const int g    = lane >> 2;
    const int t    = lane & 3;
    const int j    = lane >> 3;
    const int jr   = lane & 7;
    const int r0   = blockIdx.x * BM;
    const int ks   = blockIdx.y;
    const int kb0g = ks * (M >> 1);
    const float c  = load_hyper_c(hc);
    const float negc = -c;

    if (tid < BM) rowsum_s[tid] = 0.0f;

    const int T = M / (2 * BN);
    const size_t tile0 = (size_t)(r0 >> 6) * (M / BN) + (size_t)ks * T;

#pragma unroll
    for (int p = 0; p < 2; p++) {
        if (p < T) {
#pragma unroll
            for (int w = 0; w < 4; w++) {
                int chunk = tid + w * 256;
                int row = chunk >> 3, c8 = chunk & 7;
                cp_async16(sb + (uint32_t)(p * 16384) + swz(row, c8 * 16),
                           g_Kh + (size_t)(kb0g + p * BN + row) * D + c8 * 8);
            }
        }
        cp_commit();
    }

#pragma unroll
    for (int w = 0; w < 2; w++) {
        int chunk = tid + w * 256;
        int row = chunk >> 3, c8 = chunk & 7;
        uint4 val = reinterpret_cast<const uint4*>(g_Qh + (size_t)(r0 + row) * D)[c8];
        *reinterpret_cast<uint4*>(smem_raw + S_QOFF + swz(row, c8 * 16)) = val;
    }
    __syncthreads();

    uint32_t qa[4][2][4];
#pragma unroll
    for (int kc = 0; kc < 4; kc++) {
#pragma unroll
        for (int f = 0; f < 2; f++) {
            int row = rg * 32 + f * 16 + (j & 1) * 8 + jr;
            int col = kc * 16 + (j >> 1) * 8;
            ldsm_x4(qa[kc][f][0], qa[kc][f][1], qa[kc][f][2], qa[kc][f][3],
                    sb + S_QOFF + swz(row, col * 2));
        }
    }

    float rs[2][2] = {{0.f, 0.f}, {0.f, 0.f}};

    for (int tt = 0; tt < T; tt++) {
        const uint32_t cb = sb + (uint32_t)((tt % 3) * 16384);
        cp_wait1();
        __syncthreads();

        if (tt + 2 < T) {
            const uint32_t nb = sb + (uint32_t)(((tt + 2) % 3) * 16384);
            const int mn = (tt + 2) * BN;
#pragma unroll
            for (int w = 0; w < 4; w++) {
                int chunk = tid + w * 256;
                int row = chunk >> 3, c8 = chunk & 7;
                cp_async16(nb + swz(row, c8 * 16),
                           g_Kh + (size_t)(kb0g + mn + row) * D + c8 * 8);
            }
        }
        cp_commit();

        float sacc[2][4][4];
#pragma unroll
        for (int f = 0; f < 2; f++)
#pragma unroll
            for (int nt = 0; nt < 4; nt++)
#pragma unroll
                for (int jj = 0; jj < 4; jj++) sacc[f][nt][jj] = 0.0f;

#pragma unroll
        for (int kc = 0; kc < 4; kc++) {
#pragma unroll
            for (int ntp = 0; ntp < 2; ntp++) {
                uint32_t b0, b1, b2, b3;
                int key = kg * 32 + (2 * ntp + (j >> 1)) * 8 + jr;
                int col = kc * 16 + (j & 1) * 8;
                ldsm_x4(b0, b1, b2, b3, cb + swz(key, col * 2));
#pragma unroll
                for (int f = 0; f < 2; f++) {
                    mma_f16(sacc[f][2 * ntp + 0], qa[kc][f], b0, b1);
                    mma_f16(sacc[f][2 * ntp + 1], qa[kc][f], b2, b3);
                }
            }
        }

        // exp + rowsum + fragment-layout E store (raw e, fp16, uint4 STG)
        uint32_t* tb = g_E + (tile0 + tt) * 4096;
#pragma unroll
        for (int f = 0; f < 2; f++) {
            int g16 = rg * 2 + f;
#pragma unroll
            for (int ntp = 0; ntp < 2; ntp++) {
                float e0 = __expf(fmaf(c, sacc[f][2 * ntp][0], negc));
                float e1 = __expf(fmaf(c, sacc[f][2 * ntp][1], negc));
                float e2 = __expf(fmaf(c, sacc[f][2 * ntp][2], negc));
                float e3 = __expf(fmaf(c, sacc[f][2 * ntp][3], negc));
                float o0 = __expf(fmaf(c, sacc[f][2 * ntp + 1][0], negc));
                float o1 = __expf(fmaf(c, sacc[f][2 * ntp + 1][1], negc));
                float o2 = __expf(fmaf(c, sacc[f][2 * ntp + 1][2], negc));
                float o3 = __expf(fmaf(c, sacc[f][2 * ntp + 1][3], negc));
                rs[f][0] += (e0 + e1) + (o0 + o1);
                rs[f][1] += (e2 + e3) + (o2 + o3);
                __half2 he01 = __floats2half2_rn(e0, e1);
                __half2 he23 = __floats2half2_rn(e2, e3);
                __half2 ho01 = __floats2half2_rn(o0, o1);
                __half2 ho23 = __floats2half2_rn(o2, o3);
                uint4 pack;
                pack.x = *reinterpret_cast<uint32_t*>(&he01);
                pack.y = *reinterpret_cast<uint32_t*>(&he23);
                pack.z = *reinterpret_cast<uint32_t*>(&ho01);
                pack.w = *reinterpret_cast<uint32_t*>(&ho23);
                uint32_t* dst = tb + g16 * 1024 + (kg * 2 + ntp) * 128 + lane * 4;
                *reinterpret_cast<uint4*>(dst) = pack;
            }
        }
    }

#pragma unroll
    for (int f = 0; f < 2; f++) {
#pragma unroll
        for (int o = 1; o <= 2; o <<= 1) {
            rs[f][0] += __shfl_xor_sync(0xffffffffu, rs[f][0], o);
            rs[f][1] += __shfl_xor_sync(0xffffffffu, rs[f][1], o);
        }
        if (t == 0) {
            atomicAdd(&rowsum_s[rg * 32 + f * 16 + g], rs[f][0]);
            atomicAdd(&rowsum_s[rg * 32 + f * 16 + g + 8], rs[f][1]);
        }
    }
    __syncthreads();

    if (tid < BM) atomicAdd(&g_rowsum[r0 + tid], rowsum_s[tid]);
}

// ---------------------------------------------------------------------------
// Kernel 2b: invert rowsums.
// ---------------------------------------------------------------------------
__global__ void inv_kernel(int N) {
    int i = blockIdx.x * blockDim.x + threadIdx.x;
    if (i < N) g_invsum[i] = 1.0f / g_rowsum[i];
}

// ---------------------------------------------------------------------------
// Kernel 3: streaming PV + p writeback (R12 version: grid N/64, NO key-split).
// E tiles read linear (fragment layout -> LDS.128 A-frags), V via ldmatrix.
// p stores streaming (.cs); O written directly to out_res.
// 8 warps = 4 row-groups (16 rows) x 2 d-groups (32 d). Disjoint O ownership.
// ---------------------------------------------------------------------------
__global__ __launch_bounds__(256)
void strip_kernel(float* __restrict__ out_res,
                  float* __restrict__ out_p,
                  int N, int M) {
    extern __shared__ __align__(16) char smem_raw[];
    const uint32_t sb = smem_u32(smem_raw);

    const int tid  = threadIdx.x;
    const int lane = tid & 31;
    const int wid  = tid >> 5;
    const int rg   = wid >> 1;     // 0..3: rows [rg*16, rg*16+16)
    const int dg   = wid & 1;      // 0..1: d cols [dg*32, dg*32+32)
    const int g    = lane >> 2;
    const int t    = lane & 3;
    const int j    = lane >> 3;
    const int jr   = lane & 7;
    const int r0   = blockIdx.x * BM;

    const float inv_lo = g_invsum[r0 + rg * 16 + g];
    const float inv_hi = g_invsum[r0 + rg * 16 + g + 8];

    const int T = M / BN;
    const size_t tile0 = (size_t)(r0 >> 6) * T;
    const char* ebase_g = reinterpret_cast<const char*>(g_E);

    // prologue: prefetch E (linear) and V (swizzled) tiles 0,1
#pragma unroll
    for (int p = 0; p < 2; p++) {
        if (p < T) {
            const char* esrc = ebase_g + (tile0 + p) * 16384;
#pragma unroll
            for (int w = 0; w < 4; w++) {
                int ch = tid + w * 256;               // 0..1023
                cp_async16(sb + (uint32_t)(p * 16384 + ch * 16), esrc + ch * 16);
                int row = ch >> 3, c8 = ch & 7;
                cp_async16(sb + (uint32_t)(T_VOFF + p * 16384) + swz(row, c8 * 16),
                           g_Vh + (size_t)(p * BN + row) * D + c8 * 8);
            }
        }
        cp_commit();
    }

    float oacc[4][4];
#pragma unroll
    for (int n = 0; n < 4; n++)
#pragma unroll
        for (int jj = 0; jj < 4; jj++) oacc[n][jj] = 0.0f;

    for (int tt = 0; tt < T; tt++) {
        const uint32_t eb = sb + (uint32_t)((tt % 3) * 16384);
        const uint32_t vb = sb + (uint32_t)(T_VOFF + (tt % 3) * 16384);
        const int m0 = tt * BN;

        cp_wait1();
        __syncthreads();

        if (tt + 2 < T) {
            const char* esrc = ebase_g + (tile0 + tt + 2) * 16384;
            const uint32_t ne = sb + (uint32_t)(((tt + 2) % 3) * 16384);
            const uint32_t nv = sb + (uint32_t)(T_VOFF + ((tt + 2) % 3) * 16384);
            const int mn = (tt + 2) * BN;
#pragma unroll
            for (int w = 0; w < 4; w++) {
                int ch = tid + w * 256;
                cp_async16(ne + ch * 16, esrc + ch * 16);
                int row = ch >> 3, c8 = ch & 7;
                cp_async16(nv + swz(row, c8 * 16),
                           g_Vh + (size_t)(mn + row) * D + c8 * 8);
            }
        }
        cp_commit();

#pragma unroll
        for (int kc = 0; kc < 8; kc++) {
            // A-fragment: direct LDS.128 from fragment-layout E tile
            uint32_t u[4];
            lds128(u, eb + (uint32_t)(rg * 4096 + kc * 512 + lane * 16));

            // B-fragments: V tile, 16 keys x 32 d for this kc/dg
            uint32_t b0, b1, b2, b3, c0, c1, c2, c3;
            int key = kc * 16 + (j & 1) * 8 + jr;
            ldsm_x4_trans(b0, b1, b2, b3,
                          vb + swz(key, (dg * 4 + 0 + (j >> 1)) * 16));
            ldsm_x4_trans(c0, c1, c2, c3,
                          vb + swz(key, (dg * 4 + 2 + (j >> 1)) * 16));
            mma_f16(oacc[0], u, b0, b1);
            mma_f16(oacc[1], u, b2, b3);
            mma_f16(oacc[2], u, c0, c1);
            mma_f16(oacc[3], u, c2, c3);

            // p writeback (streaming): each dg warp handles 4 of 8 key-chunks
            if ((kc >> 2) == dg) {
                float2 f0 = __half22float2(*reinterpret_cast<__half2*>(&u[0]));
                float2 f1 = __half22float2(*reinterpret_cast<__half2*>(&u[1]));
                float2 f2 = __half22float2(*reinterpret_cast<__half2*>(&u[2]));
                float2 f3 = __half22float2(*reinterpret_cast<__half2*>(&u[3]));
                size_t rlo = (size_t)(r0 + rg * 16 + g) * M;
                size_t rhi = rlo + 8 * (size_t)M;
                int colb = m0 + kc * 16 + 2 * t;
                stcs_f2(out_p + rlo + colb,     f0.x * inv_lo, f0.y * inv_lo);
                stcs_f2(out_p + rhi + colb,     f1.x * inv_hi, f1.y * inv_hi);
                stcs_f2(out_p + rlo + colb + 8, f2.x * inv_lo, f2.y * inv_lo);
                stcs_f2(out_p + rhi + colb + 8, f3.x * inv_hi, f3.y * inv_hi);
            }
        }
    }

    // O epilogue: each warp owns rows rg*16.. x cols dg*32.. exclusively.
    int rowlo = r0 + rg * 16 + g;
#pragma unroll
    for (int n = 0; n < 4; n++) {
        int col = dg * 32 + n * 8 + 2 * t;
        stcs_f2(out_res + (size_t)rowlo * D + col,
                oacc[n][0] * inv_lo, oacc[n][1] * inv_lo);
        stcs_f2(out_res + (size_t)(rowlo + 8) * D + col,
                oacc[n][2] * inv_hi, oacc[n][3] * inv_hi);
    }
}

// ---------------------------------------------------------------------------
extern "C" void kernel_launch(void* const* d_in, const int* in_sizes, int n_in,
                              void* d_out, int out_size) {
    const float* q  = (const float*)d_in[0];
    const float* k  = (const float*)d_in[1];
    const float* v  = (const float*)d_in[2];
    const int*   hc = (const int*)d_in[3];

    int N = in_sizes[0] / D;
    int M = in_sizes[1] / D;

    float* out_res = (float*)d_out;                      // [N, D]
    float* out_p   = (float*)d_out + (size_t)N * D;      // [N, M]

    static bool attr_set = false;
    if (!attr_set) {
        cudaFuncSetAttribute(sum_kernel,
                             cudaFuncAttributeMaxDynamicSharedMemorySize, S_SMEM);
        cudaFuncSetAttribute(strip_kernel,
                             cudaFuncAttributeMaxDynamicSharedMemorySize, T_SMEM);
        attr_set = true;
    }

    int rows = N + 2 * M;
    int prep_blocks = (rows * 32 + 255) / 256;
    prep_kernel<<<prep_blocks, 256>>>(q, k, v, N, M);

    dim3 sgrid(N / BM, 2);
    sum_kernel<<<sgrid, 256, S_SMEM>>>(hc, N, M);
    inv_kernel<<<(N + 255) / 256, 256>>>(N);

    strip_kernel<<<N / BM, 256, T_SMEM>>>(out_res, out_p, N, M);
}

// round 15
// speedup vs baseline: 1.0734x; 1.0702x over previous
#include <cuda_runtime.h>
#include <cuda_fp16.h>
#include <cstdint>
#include <math.h>

#define D     64
#define MAXN  8192
#define BM    64
#define BN    128

// fused kernel dynamic smem:
//  phase A: 3 K bufs [0,48K) + Q stage [49152, 57344)
//  phase B: 3 E bufs [0,48K) + 3 V bufs [49152, 98304)
#define F_QOFF   49152
#define F_VOFF   49152
#define F_SMEM   98304

// Scratch (allocation-free contract: __device__ globals)
__device__ __align__(16) __half g_Qh[(size_t)MAXN * D];
__device__ __align__(16) __half g_Kh[(size_t)MAXN * D];
__device__ __align__(16) __half g_Vh[(size_t)MAXN * D];
// E scratch in fragment layout: per tile 4096 uint32 =
// [g16 0..3][kc 0..7][lane 0..31][slot 0..3]
__device__ __align__(16) uint32_t g_E[(size_t)(MAXN / 64) * (MAXN / 128) * 4096];

__device__ __forceinline__ float load_hyper_c(const int* hc) {
    int iv = hc[0];
    if (iv > 1000000 || iv < -1000000) return __int_as_float(iv);
    return (float)iv;
}

__device__ __forceinline__ uint32_t smem_u32(const void* p) {
    return (uint32_t)__cvta_generic_to_shared(p);
}

// Swizzled byte offset inside a tile whose rows are 128B (64 halves).
__device__ __forceinline__ uint32_t swz(int row, int colbyte) {
    return (uint32_t)(row * 128 + (colbyte ^ ((row & 7) << 4)));
}

__device__ __forceinline__ void ldsm_x4(uint32_t& r0, uint32_t& r1,
                                        uint32_t& r2, uint32_t& r3,
                                        uint32_t addr) {
    asm volatile("ldmatrix.sync.aligned.m8n8.x4.shared.b16 {%0,%1,%2,%3}, [%4];\n"
                 : "=r"(r0), "=r"(r1), "=r"(r2), "=r"(r3) : "r"(addr));
}

__device__ __forceinline__ void ldsm_x4_trans(uint32_t& r0, uint32_t& r1,
                                              uint32_t& r2, uint32_t& r3,
                                              uint32_t addr) {
    asm volatile("ldmatrix.sync.aligned.m8n8.x4.trans.shared.b16 {%0,%1,%2,%3}, [%4];\n"
                 : "=r"(r0), "=r"(r1), "=r"(r2), "=r"(r3) : "r"(addr));
}

__device__ __forceinline__ void lds128(uint32_t u[4], uint32_t addr) {
    asm volatile("ld.shared.v4.b32 {%0,%1,%2,%3}, [%4];\n"
                 : "=r"(u[0]), "=r"(u[1]), "=r"(u[2]), "=r"(u[3]) : "r"(addr));
}

__device__ __forceinline__ void mma_f16(float d[4], const uint32_t a[4],
                                        uint32_t b0, uint32_t b1) {
    asm volatile(
        "mma.sync.aligned.m16n8k16.row.col.f32.f16.f16.f32 "
        "{%0,%1,%2,%3}, {%4,%5,%6,%7}, {%8,%9}, {%0,%1,%2,%3};\n"
        : "+f"(d[0]), "+f"(d[1]), "+f"(d[2]), "+f"(d[3])
        : "r"(a[0]), "r"(a[1]), "r"(a[2]), "r"(a[3]), "r"(b0), "r"(b1));
}

__device__ __forceinline__ void cp_async16(uint32_t smem_dst, const void* gmem_src) {
    asm volatile("cp.async.cg.shared.global [%0], [%1], 16;\n"
                 :: "r"(smem_dst), "l"(gmem_src) : "memory");
}
__device__ __forceinline__ void cp_commit() {
    asm volatile("cp.async.commit_group;\n" ::: "memory");
}
__device__ __forceinline__ void cp_wait1() {
    asm volatile("cp.async.wait_group 1;\n" ::: "memory");
}
__device__ __forceinline__ void cp_wait0() {
    asm volatile("cp.async.wait_group 0;\n" ::: "memory");
}

// streaming (evict-first) float2 store: keep p out of L2 so E stays resident
__device__ __forceinline__ void stcs_f2(float* p, float x, float y) {
    asm volatile("st.global.cs.v2.f32 [%0], {%1,%2};\n"
                 :: "l"(p), "f"(x), "f"(y) : "memory");
}

// ---------------------------------------------------------------------------
// Kernel 1: normalize Q,K rows -> fp16; convert V -> fp16. One warp per row.
// ---------------------------------------------------------------------------
__global__ void prep_kernel(const float* __restrict__ q,
                            const float* __restrict__ k,
                            const float* __restrict__ v,
                            int N, int M) {
    int gw   = (blockIdx.x * blockDim.x + threadIdx.x) >> 5;
    int lane = threadIdx.x & 31;
    if (gw >= N + 2 * M) return;

    const float* src;
    __half* dst;
    bool nrm = true;
    if (gw < N)          { src = q + (size_t)gw * D;               dst = g_Qh + (size_t)gw * D; }
    else if (gw < N + M) { size_t r = gw - N;     src = k + r * D; dst = g_Kh + r * D; }
    else                 { size_t r = gw - N - M; src = v + r * D; dst = g_Vh + r * D; nrm = false; }

    float2 val = reinterpret_cast<const float2*>(src)[lane];
    float inv = 1.0f;
    if (nrm) {
        float ss = val.x * val.x + val.y * val.y;
#pragma unroll
        for (int o = 16; o > 0; o >>= 1) ss += __shfl_xor_sync(0xffffffffu, ss, o);
        inv = rsqrtf(ss);
    }
    reinterpret_cast<__half2*>(dst)[lane] = __floats2half2_rn(val.x * inv, val.y * inv);
}

// ---------------------------------------------------------------------------
// Fused kernel: per CTA (64 rows):
//  Phase A: QK + exp + rowsum over ALL key tiles; E -> g_E (fragment layout).
//  (rowsum is CTA-local: this CTA covers all keys for its rows.)
//  Phase B: PV + p writeback, reading E in REVERSE tile order (freshest tiles
//  still L2-resident). No global sync or atomics anywhere.
// ---------------------------------------------------------------------------
__global__ __launch_bounds__(256)
void fused_kernel(const int* __restrict__ hc,
                  float* __restrict__ out_res,
                  float* __restrict__ out_p,
                  int N, int M) {
    extern __shared__ __align__(16) char smem_raw[];
    const uint32_t sb = smem_u32(smem_raw);
    __shared__ float rowsum_s[BM];

    const int tid  = threadIdx.x;
    const int lane = tid & 31;
    const int wid  = tid >> 5;
    const int g    = lane >> 2;
    const int t    = lane & 3;
    const int j    = lane >> 3;
    const int jr   = lane & 7;
    const int r0   = blockIdx.x * BM;
    const float c  = load_hyper_c(hc);
    const float negc = -c;

    const int T = M / BN;
    const size_t tile0 = (size_t)(r0 >> 6) * T;

    if (tid < BM) rowsum_s[tid] = 0.0f;

    // ======================= PHASE A: QK + exp + E =======================
    {
        const int rg = wid >> 2;      // 0..1: rows [rg*32, rg*32+32)
        const int kg = wid & 3;       // 0..3: keys [kg*32, kg*32+32)

        // prefetch K tiles 0,1
#pragma unroll
        for (int p = 0; p < 2; p++) {
#pragma unroll
            for (int w = 0; w < 4; w++) {
                int chunk = tid + w * 256;
                int row = chunk >> 3, c8 = chunk & 7;
                cp_async16(sb + (uint32_t)(p * 16384) + swz(row, c8 * 16),
                           g_Kh + (size_t)(p * BN + row) * D + c8 * 8);
            }
            cp_commit();
        }

        // stage Q
#pragma unroll
        for (int w = 0; w < 2; w++) {
            int chunk = tid + w * 256;
            int row = chunk >> 3, c8 = chunk & 7;
            uint4 val = reinterpret_cast<const uint4*>(g_Qh + (size_t)(r0 + row) * D)[c8];
            *reinterpret_cast<uint4*>(smem_raw + F_QOFF + swz(row, c8 * 16)) = val;
        }
        __syncthreads();

        uint32_t qa[4][2][4];
#pragma unroll
        for (int kc = 0; kc < 4; kc++) {
#pragma unroll
            for (int f = 0; f < 2; f++) {
                int row = rg * 32 + f * 16 + (j & 1) * 8 + jr;
                int col = kc * 16 + (j >> 1) * 8;
                ldsm_x4(qa[kc][f][0], qa[kc][f][1], qa[kc][f][2], qa[kc][f][3],
                        sb + F_QOFF + swz(row, col * 2));
            }
        }

        float rs[2][2] = {{0.f, 0.f}, {0.f, 0.f}};

        for (int tt = 0; tt < T; tt++) {
            const uint32_t cb = sb + (uint32_t)((tt % 3) * 16384);
            cp_wait1();
            __syncthreads();

            if (tt + 2 < T) {
                const uint32_t nb = sb + (uint32_t)(((tt + 2) % 3) * 16384);
                const int mn = (tt + 2) * BN;
#pragma unroll
                for (int w = 0; w < 4; w++) {
                    int chunk = tid + w * 256;
                    int row = chunk >> 3, c8 = chunk & 7;
                    cp_async16(nb + swz(row, c8 * 16),
                               g_Kh + (size_t)(mn + row) * D + c8 * 8);
                }
            }
            cp_commit();

            float sacc[2][4][4];
#pragma unroll
            for (int f = 0; f < 2; f++)
#pragma unroll
                for (int nt = 0; nt < 4; nt++)
#pragma unroll
                    for (int jj = 0; jj < 4; jj++) sacc[f][nt][jj] = 0.0f;

#pragma unroll
            for (int kc = 0; kc < 4; kc++) {
#pragma unroll
                for (int ntp = 0; ntp < 2; ntp++) {
                    uint32_t b0, b1, b2, b3;
                    int key = kg * 32 + (2 * ntp + (j >> 1)) * 8 + jr;
                    int col = kc * 16 + (j & 1) * 8;
                    ldsm_x4(b0, b1, b2, b3, cb + swz(key, col * 2));
#pragma unroll
                    for (int f = 0; f < 2; f++) {
                        mma_f16(sacc[f][2 * ntp + 0], qa[kc][f], b0, b1);
                        mma_f16(sacc[f][2 * ntp + 1], qa[kc][f], b2, b3);
                    }
                }
            }

            // exp + rowsum + fragment-layout E store (uint4 STG)
            uint32_t* tb = g_E + (tile0 + tt) * 4096;
#pragma unroll
            for (int f = 0; f < 2; f++) {
                int g16 = rg * 2 + f;
#pragma unroll
                for (int ntp = 0; ntp < 2; ntp++) {
                    float e0 = __expf(fmaf(c, sacc[f][2 * ntp][0], negc));
                    float e1 = __expf(fmaf(c, sacc[f][2 * ntp][1], negc));
                    float e2 = __expf(fmaf(c, sacc[f][2 * ntp][2], negc));
                    float e3 = __expf(fmaf(c, sacc[f][2 * ntp][3], negc));
                    float o0 = __expf(fmaf(c, sacc[f][2 * ntp + 1][0], negc));
                    float o1 = __expf(fmaf(c, sacc[f][2 * ntp + 1][1], negc));
                    float o2 = __expf(fmaf(c, sacc[f][2 * ntp + 1][2], negc));
                    float o3 = __expf(fmaf(c, sacc[f][2 * ntp + 1][3], negc));
                    rs[f][0] += (e0 + e1) + (o0 + o1);
                    rs[f][1] += (e2 + e3) + (o2 + o3);
                    __half2 he01 = __floats2half2_rn(e0, e1);
                    __half2 he23 = __floats2half2_rn(e2, e3);
                    __half2 ho01 = __floats2half2_rn(o0, o1);
                    __half2 ho23 = __floats2half2_rn(o2, o3);
                    uint4 pack;
                    pack.x = *reinterpret_cast<uint32_t*>(&he01);
                    pack.y = *reinterpret_cast<uint32_t*>(&he23);
                    pack.z = *reinterpret_cast<uint32_t*>(&ho01);
                    pack.w = *reinterpret_cast<uint32_t*>(&ho23);
                    uint32_t* dst = tb + g16 * 1024 + (kg * 2 + ntp) * 128 + lane * 4;
                    *reinterpret_cast<uint4*>(dst) = pack;
                }
            }
        }
        cp_wait0();   // drain leftover prefetch groups before buffer reuse

#pragma unroll
        for (int f = 0; f < 2; f++) {
#pragma unroll
            for (int o = 1; o <= 2; o <<= 1) {
                rs[f][0] += __shfl_xor_sync(0xffffffffu, rs[f][0], o);
                rs[f][1] += __shfl_xor_sync(0xffffffffu, rs[f][1], o);
            }
            if (t == 0) {
                atomicAdd(&rowsum_s[rg * 32 + f * 16 + g], rs[f][0]);
                atomicAdd(&rowsum_s[rg * 32 + f * 16 + g + 8], rs[f][1]);
            }
        }
        __syncthreads();   // rowsum final; E writes CTA-visible; smem reusable
    }

    // ======================= PHASE B: PV + p (reverse) ====================
    {
        const int rg = wid >> 1;      // 0..3: rows [rg*16, rg*16+16)
        const int dg = wid & 1;       // 0..1: d cols [dg*32, dg*32+32)

        const float inv_lo = 1.0f / rowsum_s[rg * 16 + g];
        const float inv_hi = 1.0f / rowsum_s[rg * 16 + g + 8];

        const char* ebase_g = reinterpret_cast<const char*>(g_E);

        // prologue: prefetch tiles T-1, T-2 (reverse order)
#pragma unroll
        for (int p = 0; p < 2; p++) {
            int tp = T - 1 - p;
            const char* esrc = ebase_g + (tile0 + tp) * 16384;
            const uint32_t ebuf = sb + (uint32_t)((tp % 3) * 16384);
            const uint32_t vbuf = sb + (uint32_t)(F_VOFF + (tp % 3) * 16384);
#pragma unroll
            for (int w = 0; w < 4; w++) {
                int ch = tid + w * 256;
                cp_async16(ebuf + ch * 16, esrc + ch * 16);
                int row = ch >> 3, c8 = ch & 7;
                cp_async16(vbuf + swz(row, c8 * 16),
                           g_Vh + (size_t)(tp * BN + row) * D + c8 * 8);
            }
            cp_commit();
        }

        float oacc[4][4];
#pragma unroll
        for (int n = 0; n < 4; n++)
#pragma unroll
            for (int jj = 0; jj < 4; jj++) oacc[n][jj] = 0.0f;

        for (int tt = T - 1; tt >= 0; tt--) {
            const uint32_t eb = sb + (uint32_t)((tt % 3) * 16384);
            const uint32_t vb = sb + (uint32_t)(F_VOFF + (tt % 3) * 16384);
            const int m0 = tt * BN;

            cp_wait1();
            __syncthreads();

            if (tt - 2 >= 0) {
                const int tp = tt - 2;
                const char* esrc = ebase_g + (tile0 + tp) * 16384;
                const uint32_t ne = sb + (uint32_t)((tp % 3) * 16384);
                const uint32_t nv = sb + (uint32_t)(F_VOFF + (tp % 3) * 16384);
#pragma unroll
                for (int w = 0; w < 4; w++) {
                    int ch = tid + w * 256;
                    cp_async16(ne + ch * 16, esrc + ch * 16);
                    int row = ch >> 3, c8 = ch & 7;
                    cp_async16(nv + swz(row, c8 * 16),
                               g_Vh + (size_t)(tp * BN + row) * D + c8 * 8);
                }
            }
            cp_commit();

#pragma unroll
            for (int kc = 0; kc < 8; kc++) {
                // A-fragment: direct LDS.128 from fragment-layout E tile
                uint32_t u[4];
                lds128(u, eb + (uint32_t)(rg * 4096 + kc * 512 + lane * 16));

                // B-fragments: V tile, 16 keys x 32 d for this kc/dg
                uint32_t b0, b1, b2, b3, c0, c1, c2, c3;
                int key = kc * 16 + (j & 1) * 8 + jr;
                ldsm_x4_trans(b0, b1, b2, b3,
                              vb + swz(key, (dg * 4 + 0 + (j >> 1)) * 16));
                ldsm_x4_trans(c0, c1, c2, c3,
                              vb + swz(key, (dg * 4 + 2 + (j >> 1)) * 16));
                mma_f16(oacc[0], u, b0, b1);
                mma_f16(oacc[1], u, b2, b3);
                mma_f16(oacc[2], u, c0, c1);
                mma_f16(oacc[3], u, c2, c3);

                // p writeback (streaming): each dg warp handles 4 of 8 chunks
                if ((kc >> 2) == dg) {
                    float2 f0 = __half22float2(*reinterpret_cast<__half2*>(&u[0]));
                    float2 f1 = __half22float2(*reinterpret_cast<__half2*>(&u[1]));
                    float2 f2 = __half22float2(*reinterpret_cast<__half2*>(&u[2]));
                    float2 f3 = __half22float2(*reinterpret_cast<__half2*>(&u[3]));
                    size_t rlo = (size_t)(r0 + rg * 16 + g) * M;
                    size_t rhi = rlo + 8 * (size_t)M;
                    int colb = m0 + kc * 16 + 2 * t;
                    stcs_f2(out_p + rlo + colb,     f0.x * inv_lo, f0.y * inv_lo);
                    stcs_f2(out_p + rhi + colb,     f1.x * inv_hi, f1.y * inv_hi);
                    stcs_f2(out_p + rlo + colb + 8, f2.x * inv_lo, f2.y * inv_lo);
                    stcs_f2(out_p + rhi + colb + 8, f3.x * inv_hi, f3.y * inv_hi);
                }
            }
        }

        // O epilogue: each warp owns rows rg*16.. x cols dg*32.. exclusively.
        int rowlo = r0 + rg * 16 + g;
#pragma unroll
        for (int n = 0; n < 4; n++) {
            int col = dg * 32 + n * 8 + 2 * t;
            stcs_f2(out_res + (size_t)rowlo * D + col,
                    oacc[n][0] * inv_lo, oacc[n][1] * inv_lo);
            stcs_f2(out_res + (size_t)(rowlo + 8) * D + col,
                    oacc[n][2] * inv_hi, oacc[n][3] * inv_hi);
        }
    }
}

// ---------------------------------------------------------------------------
extern "C" void kernel_launch(void* const* d_in, const int* in_sizes, int n_in,
                              void* d_out, int out_size) {
    const float* q  = (const float*)d_in[0];
    const float* k  = (const float*)d_in[1];
    const float* v  = (const float*)d_in[2];
    const int*   hc = (const int*)d_in[3];

    int N = in_sizes[0] / D;
    int M = in_sizes[1] / D;

    float* out_res = (float*)d_out;                      // [N, D]
    float* out_p   = (float*)d_out + (size_t)N * D;      // [N, M]

    static bool attr_set = false;
    if (!attr_set) {
        cudaFuncSetAttribute(fused_kernel,
                             cudaFuncAttributeMaxDynamicSharedMemorySize, F_SMEM);
        attr_set = true;
    }

    int rows = N + 2 * M;
    int prep_blocks = (rows * 32 + 255) / 256;
    prep_kernel<<<prep_blocks, 256>>>(q, k, v, N, M);

    fused_kernel<<<N / BM, 256, F_SMEM>>>(hc, out_res, out_p, N, M);
}